// round 4
// baseline (speedup 1.0000x reference)
#include <cuda_runtime.h>
#include <cstdint>
#include <cstddef>

#define T_STEPS 4096
#define IN_DIM  128
#define HIDDEN  2048
#define LEAK    0.9f
#define NCTA    128
#define TPB     512
#define ROWS_PER_CTA 16   // HIDDEN / NCTA

// ---------------- device scratch (static: no allocations allowed) ----------------
__device__ float g_inp[(size_t)T_STEPS * HIDDEN];   // precomputed input projection [T,H]
__device__ float g_actbuf[2][HIDDEN];               // double-buffered activation vector
__device__ unsigned int g_arrive[NCTA];             // per-CTA arrival slots (monotonic across replays)

// ---------------- packed fp32x2 helpers ----------------
__device__ __forceinline__ unsigned long long pack2(float lo, float hi) {
    unsigned long long u;
    asm("mov.b64 %0, {%1, %2};" : "=l"(u) : "f"(lo), "f"(hi));
    return u;
}
__device__ __forceinline__ void unpack2(unsigned long long u, float& lo, float& hi) {
    asm("mov.b64 {%0, %1}, %2;" : "=f"(lo), "=f"(hi) : "l"(u));
}
__device__ __forceinline__ unsigned long long ffma2(unsigned long long a,
                                                    unsigned long long b,
                                                    unsigned long long c) {
    unsigned long long d;
    asm("fma.rn.f32x2 %0, %1, %2, %3;" : "=l"(d) : "l"(a), "l"(b), "l"(c));
    return d;
}

// ---------------- barrier primitives: distributed slots, no RMW ----------------
__device__ __forceinline__ void st_release_u32(unsigned int* p, unsigned int v) {
    asm volatile("st.release.gpu.global.u32 [%0], %1;" :: "l"(p), "r"(v) : "memory");
}
__device__ __forceinline__ void ld_volatile_v4(const unsigned int* p,
                                               unsigned int& a, unsigned int& b,
                                               unsigned int& c, unsigned int& d) {
    asm volatile("ld.volatile.global.v4.u32 {%0,%1,%2,%3}, [%4];"
                 : "=r"(a), "=r"(b), "=r"(c), "=r"(d) : "l"(p) : "memory");
}
__device__ __forceinline__ void fence_acq_rel_gpu() {
    asm volatile("fence.acq_rel.gpu;" ::: "memory");
}

// ---------------- phase A: inp_proj[t][h] = input[t,:] . w_ih[h,:] + b_ih[h] ----------------
__global__ void inp_proj_kernel(const float* __restrict__ input,
                                const float* __restrict__ w_ih,
                                const float* __restrict__ b_ih) {
    __shared__ float s_in[16 * IN_DIM];
    const int tblk = blockIdx.x;
    const int tid  = threadIdx.x;

    for (int i = tid; i < 16 * IN_DIM; i += 256)
        s_in[i] = input[(size_t)tblk * 16 * IN_DIM + i];
    __syncthreads();

    const float4* s_in4 = reinterpret_cast<const float4*>(s_in);

    for (int j = 0; j < 8; j++) {
        const int h = tid + 256 * j;
        float acc[16];
        const float b = b_ih[h];
#pragma unroll
        for (int t = 0; t < 16; t++) acc[t] = b;

        const float4* wrow = reinterpret_cast<const float4*>(w_ih + (size_t)h * IN_DIM);
#pragma unroll 4
        for (int kc = 0; kc < IN_DIM / 4; kc++) {
            const float4 w4 = wrow[kc];
#pragma unroll
            for (int t = 0; t < 16; t++) {
                const float4 iv = s_in4[t * (IN_DIM / 4) + kc];  // warp-broadcast
                acc[t] += w4.x * iv.x + w4.y * iv.y + w4.z * iv.z + w4.w * iv.w;
            }
        }
#pragma unroll
        for (int t = 0; t < 16; t++)
            g_inp[(size_t)(tblk * 16 + t) * HIDDEN + h] = acc[t];
    }
}

// ---------------- phase B: persistent recurrence kernel ----------------
// 128 CTAs x 512 threads. CTA b owns rows [16b, 16b+16).
// Thread tid owns ALL 16 rows x cols [4*tid, 4*tid+4) (64 weights in regs).
// Barrier: per-CTA release slot + gather-poll by warp 1 (overlapped with
// warp 0's finalize of the previous step). No atomics anywhere.
__global__ void __launch_bounds__(TPB, 1)
reservoir_kernel(const float* __restrict__ w_hh,
                 float* __restrict__ out_act,
                 float* __restrict__ out_hid) {
    __shared__ float s_part[ROWS_PER_CTA][17];   // [row][warp], padded

    const int tid  = threadIdx.x;
    const int lane = tid & 31;
    const int w    = tid >> 5;                   // warp id 0..15
    const int cta  = blockIdx.x;
    const int base_row = cta * ROWS_PER_CTA;

    // Monotonic base for this launch: own slot, sole writer -> race-free.
    const unsigned int base = g_arrive[cta];

    // Load weights: W[r] = cols [4*tid, 4*tid+4) of row base_row + r.
    unsigned long long W[ROWS_PER_CTA][2];
#pragma unroll
    for (int r = 0; r < ROWS_PER_CTA; r++) {
        const float4 wv = reinterpret_cast<const float4*>(
            w_hh + (size_t)(base_row + r) * HIDDEN)[tid];
        W[r][0] = pack2(wv.x, wv.y);
        W[r][1] = pack2(wv.z, wv.w);
    }

    const int myrow = base_row + tid;   // meaningful for tid < 16
    float hid = 0.0f;

    // ---- t = 0 peeled: act vector is zero -> dot = 0. Arrival value base+1. ----
    if (tid < ROWS_PER_CTA) {
        const float u0 = g_inp[myrow];
        const float nh = LEAK * u0;
        const float na = tanhf(nh);
        hid = nh;
        out_act[myrow] = na;
        out_hid[myrow] = nh;
        g_actbuf[1][myrow] = na;
        __syncwarp(0x0000ffffu);
        if (tid == 0) st_release_u32(&g_arrive[cta], base + 1u);
    }

    for (int t = 1; t < T_STEPS; t++) {
        // prefetch u_t (not gated by the barrier)
        float u = 0.0f;
        if (tid < ROWS_PER_CTA) u = g_inp[(size_t)t * HIDDEN + myrow];

        // ---- warp 1: gather-poll all 128 slots for act_{t-1} (value base+t) ----
        if (w == 1) {
            const unsigned int target = base + (unsigned int)t;
            bool ok;
            do {
                unsigned int s0, s1, s2, s3;
                ld_volatile_v4(g_arrive + 4 * lane, s0, s1, s2, s3);
                ok = ((int)(s0 - target) >= 0) & ((int)(s1 - target) >= 0) &
                     ((int)(s2 - target) >= 0) & ((int)(s3 - target) >= 0);
            } while (!__all_sync(0xffffffffu, ok));
            fence_acq_rel_gpu();
        }
        __syncthreads();   // (A) barrier passed; act_{t-1} visible

        // act slice straight into registers (L2-coherent load)
        const float4 a = __ldcg(reinterpret_cast<const float4*>(g_actbuf[t & 1]) + tid);
        const unsigned long long A0 = pack2(a.x, a.y);
        const unsigned long long A1 = pack2(a.z, a.w);

        // 16 independent 2-deep FFMA2 chains
        float v[ROWS_PER_CTA];
#pragma unroll
        for (int r = 0; r < ROWS_PER_CTA; r++) {
            unsigned long long P = ffma2(W[r][0], A0, 0ull);
            P = ffma2(W[r][1], A1, P);
            float lo, hi; unpack2(P, lo, hi);
            v[r] = lo + hi;
        }

        // ---- value-splitting warp butterfly: 16 values -> 1 per lane ----
        {
            const bool up = (lane & 16) != 0;
#pragma unroll
            for (int i = 0; i < 8; i++) {
                const float send = up ? v[i] : v[i + 8];
                const float recv = __shfl_xor_sync(0xffffffffu, send, 16);
                v[i] = (up ? v[i + 8] : v[i]) + recv;
            }
        }
        {
            const bool up = (lane & 8) != 0;
#pragma unroll
            for (int i = 0; i < 4; i++) {
                const float send = up ? v[i] : v[i + 4];
                const float recv = __shfl_xor_sync(0xffffffffu, send, 8);
                v[i] = (up ? v[i + 4] : v[i]) + recv;
            }
        }
        {
            const bool up = (lane & 4) != 0;
#pragma unroll
            for (int i = 0; i < 2; i++) {
                const float send = up ? v[i] : v[i + 2];
                const float recv = __shfl_xor_sync(0xffffffffu, send, 4);
                v[i] = (up ? v[i + 2] : v[i]) + recv;
            }
        }
        {
            const bool up = (lane & 2) != 0;
            const float send = up ? v[0] : v[1];
            const float recv = __shfl_xor_sync(0xffffffffu, send, 2);
            v[0] = (up ? v[1] : v[0]) + recv;
        }
        v[0] += __shfl_xor_sync(0xffffffffu, v[0], 1);

        // lane holds row (lane>>1)&15; even lanes publish per-warp partial
        const int vrow = (lane >> 1) & 15;
        if ((lane & 1) == 0) s_part[vrow][w] = v[0];
        __syncthreads();   // (B) s_part ready

        // ---- finalize (warp 0, 16 lanes): leak + tanh + stores + arrival ----
        if (tid < ROWS_PER_CTA) {
            float d0 = 0.0f, d1 = 0.0f, d2 = 0.0f, d3 = 0.0f;
#pragma unroll
            for (int j = 0; j < 4; j++) {
                d0 += s_part[tid][j];
                d1 += s_part[tid][j + 4];
                d2 += s_part[tid][j + 8];
                d3 += s_part[tid][j + 12];
            }
            const float dot = (d0 + d1) + (d2 + d3);
            const float nh = (1.0f - LEAK) * hid + LEAK * (u + dot);
            const float na = tanhf(nh);
            hid = nh;
            out_act[(size_t)t * HIDDEN + myrow] = na;
            out_hid[(size_t)t * HIDDEN + myrow] = nh;
            g_actbuf[(t + 1) & 1][myrow] = na;
            __syncwarp(0x0000ffffu);
            if (tid == 0 && t < T_STEPS - 1)
                st_release_u32(&g_arrive[cta], base + (unsigned int)(t + 1));
        }
        // warp 1 proceeds to poll for t+1 concurrently with this finalize
    }

    // Keep slot history identical across launches: bump to base + T_STEPS - 1
    // only happened for t < T-1; final value = base + T_STEPS - 1 for all CTAs.
}

// ---------------- launch ----------------
extern "C" void kernel_launch(void* const* d_in, const int* in_sizes, int n_in,
                              void* d_out, int out_size) {
    const float* input = (const float*)d_in[0];   // [T, IN_DIM]
    const float* w_ih  = (const float*)d_in[1];   // [H, IN_DIM]
    const float* b_ih  = (const float*)d_in[2];   // [H]
    const float* w_hh  = (const float*)d_in[3];   // [H, H]

    float* out_act = (float*)d_out;                            // [T, H]
    float* out_hid = (float*)d_out + (size_t)T_STEPS * HIDDEN; // [T, H]

    inp_proj_kernel<<<T_STEPS / 16, 256>>>(input, w_ih, b_ih);
    reservoir_kernel<<<NCTA, TPB>>>(w_hh, out_act, out_hid);
}